// round 14
// baseline (speedup 1.0000x reference)
#include <cuda_runtime.h>
#include <cstdint>

#define ROWS   4096
#define FDIM   16384
#define BINS   128
#define NFEAT  257
#define OUT    64
#define HB     512
#define NW     (HB / 32)      // 16 warps
#define NCOPY  16             // per-warp histogram copies

// Written by wave-1 CTAs before their main pass; read by all epilogues (later)
__device__ __align__(16) float g_WTc[BINS * OUT];   // counts-part W, transposed [i][j]
__device__ __align__(16) float g_u[OUT];            // sum_k W[j][128+k]
__device__ __align__(16) float g_v[OUT];            // sum_k (k/128) W[j][128+k]

// ---------------------------------------------------------------------------
// Single fused kernel:
//   pass 1: LDG float4 sweep (one DRAM pass) -> min/max in regs, STS row->smem
//   pass 2: LDS sweep -> bin into per-warp private hist (plain atomics)
//   epilogue: counts dot WTc + linear boundary fold (u, v)
// Dynamic smem: [0,64K) row | [64K,72K) aux (hist, then s_cnt+spart aliased)
// ---------------------------------------------------------------------------
__global__ __launch_bounds__(HB, 3) void fused_kernel(const float* __restrict__ x,
                                                      const float* __restrict__ W,
                                                      const float* __restrict__ bias,
                                                      float* __restrict__ out) {
    extern __shared__ __align__(16) float sdata[];          // row: 16384 floats
    float* aux = sdata + FDIM;
    unsigned int* hist = reinterpret_cast<unsigned int*>(aux);   // 8 KB

    __shared__ float s_red[2 * NW];
    __shared__ float s_mnw[2];

    const int row  = blockIdx.x;
    const int tid  = threadIdx.x;
    const int warp = tid >> 5;
    const int lane = tid & 31;

    // zero per-warp histogram copies
    #pragma unroll
    for (int k = 0; k < (NCOPY * BINS) / HB; k++)
        hist[tid + k * HB] = 0u;

    // ---- one-time W prep (wave-1 CTAs; epilogue readers run much later) ----
    if (row < OUT) {
        if (tid < BINS) g_WTc[tid * OUT + row] = W[row * NFEAT + tid];
        if (tid == 0) __threadfence();
    } else if (row < 2 * OUT) {
        const int j = row - OUT;
        if (warp == 0) {
            const float* wb = W + j * NFEAT + BINS;      // W[j][128..256]
            float u = 0.0f, v = 0.0f;
            #pragma unroll
            for (int q = 0; q < 4; q++) {
                int k = q * 32 + lane;                   // 0..127
                float w = wb[k];
                u += w;
                v += (float)k * (1.0f / 128.0f) * w;
            }
            if (lane == 0) { u += wb[128]; v += wb[128]; }   // k=128 term, t=1
            #pragma unroll
            for (int o = 16; o > 0; o >>= 1) {
                u += __shfl_xor_sync(0xffffffffu, u, o);
                v += __shfl_xor_sync(0xffffffffu, v, o);
            }
            if (lane == 0) {
                g_u[j] = u;
                g_v[j] = v;
                __threadfence();
            }
        }
    }

    const float4* xr  = reinterpret_cast<const float4*>(x) + (size_t)row * (FDIM / 4);
    float4*       sd4 = reinterpret_cast<float4*>(sdata);

    // ---- pass 1: LDG -> min/max -> STS (single DRAM pass, 8-deep MLP) ----
    float mn, mx;
    {
        float4 v0 = xr[tid];
        sd4[tid] = v0;
        mn = fminf(fminf(v0.x, v0.y), fminf(v0.z, v0.w));
        mx = fmaxf(fmaxf(v0.x, v0.y), fmaxf(v0.z, v0.w));
        #pragma unroll
        for (int k = 1; k < 8; k++) {
            float4 v = xr[tid + k * HB];
            sd4[tid + k * HB] = v;
            mn = fminf(mn, fminf(fminf(v.x, v.y), fminf(v.z, v.w)));
            mx = fmaxf(mx, fmaxf(fmaxf(v.x, v.y), fmaxf(v.z, v.w)));
        }
    }
    #pragma unroll
    for (int o = 16; o > 0; o >>= 1) {
        mn = fminf(mn, __shfl_xor_sync(0xffffffffu, mn, o));
        mx = fmaxf(mx, __shfl_xor_sync(0xffffffffu, mx, o));
    }
    if (lane == 0) { s_red[warp] = mn; s_red[NW + warp] = mx; }
    __syncthreads();
    if (tid == 0) {
        float m = s_red[0], M = s_red[NW];
        #pragma unroll
        for (int i = 1; i < NW; i++) {
            m = fminf(m, s_red[i]);
            M = fmaxf(M, s_red[NW + i]);
        }
        s_mnw[0] = m;
        s_mnw[1] = M - m;
    }
    __syncthreads();

    const float row_mn = s_mnw[0];
    const float width  = s_mnw[1];
    const float invw   = 128.0f / ((width == 0.0f) ? 1.0f : width);
    const float nmn    = -row_mn * invw;

    // ---- pass 2: LDS re-read, bin into this warp's private copy ----
    // v >= mn => fma >= -1ulp, so int-trunc == floor + lower clamp.
    unsigned int* h = &hist[warp * BINS];
    const float4* sdr = reinterpret_cast<const float4*>(sdata);
    #pragma unroll
    for (int k = 0; k < 8; k++) {
        float4 v = sdr[tid + k * HB];
        float vals[4] = {v.x, v.y, v.z, v.w};
        #pragma unroll
        for (int e = 0; e < 4; e++) {
            int b = (int)__fmaf_rn(vals[e], invw, nmn);
            b = min(b, BINS - 1);
            atomicAdd(&h[b], 1u);
        }
    }
    __syncthreads();

    // reduce the 16 copies into registers, then alias the aux region
    unsigned int cnt = 0;
    if (tid < BINS) {
        #pragma unroll
        for (int c = 0; c < NCOPY; c++) cnt += hist[c * BINS + tid];
    }
    __syncthreads();                                  // hist dead

    float*  s_cnt = aux;                              // [128]
    float4* spart = reinterpret_cast<float4*>(aux + BINS);  // [16][16]

    if (tid < BINS) s_cnt[tid] = (float)cnt;
    __syncthreads();

    // ---- epilogue dot: thread = (j4 = tid&15, p = tid>>4); p covers 4 bins ----
    const int j4 = tid & 15;
    const int p  = tid >> 4;
    const float4* WTc4 = reinterpret_cast<const float4*>(g_WTc);

    float4 acc = make_float4(0.f, 0.f, 0.f, 0.f);
    #pragma unroll
    for (int k = 0; k < 4; k++) {
        int i = p * 4 + k;                            // 0..127
        float  fv = s_cnt[i];
        float4 wv = WTc4[i * (OUT / 4) + j4];
        acc.x += fv * wv.x;
        acc.y += fv * wv.y;
        acc.z += fv * wv.z;
        acc.w += fv * wv.w;
    }
    acc.x += __shfl_xor_sync(0xffffffffu, acc.x, 16);
    acc.y += __shfl_xor_sync(0xffffffffu, acc.y, 16);
    acc.z += __shfl_xor_sync(0xffffffffu, acc.z, 16);
    acc.w += __shfl_xor_sync(0xffffffffu, acc.w, 16);
    if (lane < 16) spart[warp * 16 + lane] = acc;
    __syncthreads();

    if (tid < OUT) {
        const float* sp = reinterpret_cast<const float*>(spart);  // [16][64]
        float s = 0.0f;
        #pragma unroll
        for (int w = 0; w < NW; w++) s += sp[w * OUT + tid];
        float o = s * (1.0f / 16384.0f)
                + row_mn * g_u[tid] + width * g_v[tid] + bias[tid];
        out[(size_t)row * OUT + tid] = o;
    }
}

// ---------------------------------------------------------------------------
extern "C" void kernel_launch(void* const* d_in, const int* in_sizes, int n_in,
                              void* d_out, int out_size) {
    const float* x    = (const float*)d_in[0];   // [4096, 16384]
    const float* W    = (const float*)d_in[1];   // [64, 257]
    const float* bias = (const float*)d_in[2];   // [64]
    float* out = (float*)d_out;                  // [4096, 64]

    const int dyn_smem = (FDIM + NCOPY * BINS) * 4;   // 64 KB row + 8 KB aux
    cudaFuncSetAttribute(fused_kernel, cudaFuncAttributeMaxDynamicSharedMemorySize, dyn_smem);

    fused_kernel<<<ROWS, HB, dyn_smem>>>(x, W, bias, out);
}

// round 15
// speedup vs baseline: 1.3145x; 1.3145x over previous
#include <cuda_runtime.h>
#include <cstdint>

#define ROWS   4096
#define FDIM   16384
#define HALF   8192           // floats per chunk (32 KB)
#define BINS   128
#define NFEAT  257
#define OUT    64
#define HB     512
#define NW     (HB / 32)      // 16 warps
#define NCOPY  16             // per-warp histogram copies
#define GRID   444            // 3 per SM x 148 SMs, all co-resident

// One-time W folding (written by CTAs 0..63; guarded by g_rdy flags)
__device__ __align__(16) float g_WTc[BINS * OUT];   // counts-part W, transposed [i][j]
__device__ __align__(16) float g_u[OUT];            // sum_k W[j][128+k]
__device__ __align__(16) float g_v[OUT];            // sum_k (k/128) W[j][128+k]
__device__ unsigned int g_rdy[2];                   // 64 writer bits

__device__ __forceinline__ uint32_t smem_u32(const void* p) {
    uint32_t a;
    asm("{ .reg .u64 t; cvta.to.shared.u64 t, %1; cvt.u32.u64 %0, t; }" : "=r"(a) : "l"(p));
    return a;
}

__device__ __forceinline__ void tma_issue(uint32_t dst, const float* src, uint32_t mbar) {
    asm volatile("mbarrier.arrive.expect_tx.shared.b64 _, [%0], %1;"
                 :: "r"(mbar), "r"(HALF * 4) : "memory");
    asm volatile("cp.async.bulk.shared::cta.global.mbarrier::complete_tx::bytes "
                 "[%0], [%1], %2, [%3];"
                 :: "r"(dst), "l"(src), "r"(HALF * 4), "r"(mbar) : "memory");
}

__device__ __forceinline__ void mbar_wait(uint32_t mbar, uint32_t parity) {
    uint32_t done;
    asm volatile("{\n\t.reg .pred p;\n\t"
                 "mbarrier.try_wait.parity.acquire.cta.shared::cta.b64 p, [%1], %2;\n\t"
                 "selp.b32 %0, 1, 0, p;\n\t}"
                 : "=r"(done) : "r"(mbar), "r"(parity) : "memory");
    while (!done) {
        asm volatile("{\n\t.reg .pred p;\n\t"
                     "mbarrier.try_wait.parity.acquire.cta.shared::cta.b64 p, [%1], %2, 0x989680;\n\t"
                     "selp.b32 %0, 1, 0, p;\n\t}"
                     : "=r"(done) : "r"(mbar), "r"(parity) : "memory");
    }
}

// ---------------------------------------------------------------------------
// Persistent fused kernel: 2-chunk TMA ring pipelines the next row's loads
// under the current row's binning + epilogue.
// Dynamic smem: buf0[8K f] | buf1[8K f] | aux[2K u32] (hist -> s_cnt+spart)
// ---------------------------------------------------------------------------
__global__ __launch_bounds__(HB, 3) void fused_kernel(const float* __restrict__ x,
                                                      const float* __restrict__ W,
                                                      const float* __restrict__ bias,
                                                      float* __restrict__ out) {
    extern __shared__ __align__(16) float sm[];
    float* buf0 = sm;
    float* buf1 = sm + HALF;
    float* aux  = sm + 2 * HALF;                        // 2048 floats
    unsigned int* hist = reinterpret_cast<unsigned int*>(aux);

    __shared__ float s_red[2 * NW];
    __shared__ float s_mnw[2];
    __shared__ __align__(8) unsigned long long mbar[2];

    const int bid  = blockIdx.x;
    const int tid  = threadIdx.x;
    const int warp = tid >> 5;
    const int lane = tid & 31;

    // zero hist region
    #pragma unroll
    for (int k = 0; k < 4; k++) hist[tid + k * HB] = 0u;

    const uint32_t m0 = smem_u32(&mbar[0]);
    const uint32_t m1 = smem_u32(&mbar[1]);
    const uint32_t b0a = smem_u32(buf0);
    const uint32_t b1a = smem_u32(buf1);

    if (tid == 0) {
        asm volatile("mbarrier.init.shared.b64 [%0], 1;" :: "r"(m0) : "memory");
        asm volatile("mbarrier.init.shared.b64 [%0], 1;" :: "r"(m1) : "memory");
        asm volatile("fence.proxy.async.shared::cta;" ::: "memory");
    }
    __syncthreads();

    // prologue: TMA both chunks of this CTA's first row
    if (tid == 0) {
        const float* r0 = x + (size_t)bid * FDIM;
        tma_issue(b0a, r0, m0);
        tma_issue(b1a, r0 + HALF, m1);
    }

    // ---- one-time W prep (CTAs 0..63), overlapped with prologue TMA ----
    if (bid < OUT) {
        if (tid < BINS) g_WTc[tid * OUT + bid] = W[bid * NFEAT + tid];
        if (warp == 0) {
            const float* wb = W + bid * NFEAT + BINS;    // W[bid][128..256]
            float u = 0.0f, v = 0.0f;
            #pragma unroll
            for (int q = 0; q < 4; q++) {
                int k = q * 32 + lane;                   // 0..127
                float w = wb[k];
                u += w;
                v += (float)k * (1.0f / 128.0f) * w;
            }
            if (lane == 0) { u += wb[128]; v += wb[128]; }   // k=128 term, t=1
            #pragma unroll
            for (int o = 16; o > 0; o >>= 1) {
                u += __shfl_xor_sync(0xffffffffu, u, o);
                v += __shfl_xor_sync(0xffffffffu, v, o);
            }
            if (lane == 0) { g_u[bid] = u; g_v[bid] = v; }
        }
        __syncthreads();
        if (tid == 0) {
            __threadfence();
            atomicOr(&g_rdy[bid >> 5], 1u << (bid & 31));
        }
    }

    const float4* sb0 = reinterpret_cast<const float4*>(buf0);
    const float4* sb1 = reinterpret_cast<const float4*>(buf1);

    uint32_t parity = 0;
    for (int r = bid, it = 0; r < ROWS; r += GRID, ++it, parity ^= 1u) {
        // ---- min/max over both chunks ----
        mbar_wait(m0, parity);
        float mn, mx;
        {
            float4 v0 = sb0[tid];
            mn = fminf(fminf(v0.x, v0.y), fminf(v0.z, v0.w));
            mx = fmaxf(fmaxf(v0.x, v0.y), fmaxf(v0.z, v0.w));
            #pragma unroll
            for (int k = 1; k < 4; k++) {
                float4 v = sb0[tid + k * HB];
                mn = fminf(mn, fminf(fminf(v.x, v.y), fminf(v.z, v.w)));
                mx = fmaxf(mx, fmaxf(fmaxf(v.x, v.y), fmaxf(v.z, v.w)));
            }
        }
        mbar_wait(m1, parity);
        #pragma unroll
        for (int k = 0; k < 4; k++) {
            float4 v = sb1[tid + k * HB];
            mn = fminf(mn, fminf(fminf(v.x, v.y), fminf(v.z, v.w)));
            mx = fmaxf(mx, fmaxf(fmaxf(v.x, v.y), fmaxf(v.z, v.w)));
        }
        #pragma unroll
        for (int o = 16; o > 0; o >>= 1) {
            mn = fminf(mn, __shfl_xor_sync(0xffffffffu, mn, o));
            mx = fmaxf(mx, __shfl_xor_sync(0xffffffffu, mx, o));
        }
        if (lane == 0) { s_red[warp] = mn; s_red[NW + warp] = mx; }
        __syncthreads();
        if (tid == 0) {
            float m = s_red[0], M = s_red[NW];
            #pragma unroll
            for (int i = 1; i < NW; i++) {
                m = fminf(m, s_red[i]);
                M = fmaxf(M, s_red[NW + i]);
            }
            s_mnw[0] = m;
            s_mnw[1] = M - m;
        }
        __syncthreads();

        const float row_mn = s_mnw[0];
        const float width  = s_mnw[1];
        const float invw   = 128.0f / ((width == 0.0f) ? 1.0f : width);
        const float nmn    = -row_mn * invw;

        // ---- bin chunk 0, then refill buf0 with next row's chunk 0 ----
        unsigned int* h = &hist[warp * BINS];
        #pragma unroll
        for (int k = 0; k < 4; k++) {
            float4 v = sb0[tid + k * HB];
            float vals[4] = {v.x, v.y, v.z, v.w};
            #pragma unroll
            for (int e = 0; e < 4; e++) {
                int b = (int)__fmaf_rn(vals[e], invw, nmn);
                b = min(b, BINS - 1);
                atomicAdd(&h[b], 1u);
            }
        }
        __syncthreads();
        if (tid == 0 && r + GRID < ROWS)
            tma_issue(b0a, x + (size_t)(r + GRID) * FDIM, m0);

        // ---- bin chunk 1, then refill buf1 ----
        #pragma unroll
        for (int k = 0; k < 4; k++) {
            float4 v = sb1[tid + k * HB];
            float vals[4] = {v.x, v.y, v.z, v.w};
            #pragma unroll
            for (int e = 0; e < 4; e++) {
                int b = (int)__fmaf_rn(vals[e], invw, nmn);
                b = min(b, BINS - 1);
                atomicAdd(&h[b], 1u);
            }
        }
        __syncthreads();
        if (tid == 0 && r + GRID < ROWS)
            tma_issue(b1a, x + (size_t)(r + GRID) * FDIM + HALF, m1);

        // ---- counts reduce ----
        unsigned int cnt = 0;
        if (tid < BINS) {
            #pragma unroll
            for (int c = 0; c < NCOPY; c++) cnt += hist[c * BINS + tid];
        }
        // first row only: make sure W-prep is globally visible (writers co-resident)
        if (it == 0 && tid < 2) {
            volatile unsigned int* rv = &g_rdy[tid];
            while (*rv != 0xffffffffu) {}
        }
        __syncthreads();                                  // hist dead

        float*  s_cnt = aux;                              // [128]
        float4* spart = reinterpret_cast<float4*>(aux + BINS);  // [16][16]

        if (tid < BINS) s_cnt[tid] = (float)cnt;
        __syncthreads();

        // ---- epilogue dot: (j4 = tid&15, p = tid>>4), p covers 4 bins ----
        const int j4 = tid & 15;
        const int p  = tid >> 4;
        const float4* WTc4 = reinterpret_cast<const float4*>(g_WTc);

        float4 acc = make_float4(0.f, 0.f, 0.f, 0.f);
        #pragma unroll
        for (int k = 0; k < 4; k++) {
            int i = p * 4 + k;                            // 0..127
            float  fv = s_cnt[i];
            float4 wv = WTc4[i * (OUT / 4) + j4];
            acc.x += fv * wv.x;
            acc.y += fv * wv.y;
            acc.z += fv * wv.z;
            acc.w += fv * wv.w;
        }
        acc.x += __shfl_xor_sync(0xffffffffu, acc.x, 16);
        acc.y += __shfl_xor_sync(0xffffffffu, acc.y, 16);
        acc.z += __shfl_xor_sync(0xffffffffu, acc.z, 16);
        acc.w += __shfl_xor_sync(0xffffffffu, acc.w, 16);
        if (lane < 16) spart[warp * 16 + lane] = acc;
        __syncthreads();

        if (tid < OUT) {
            const float* sp = reinterpret_cast<const float*>(spart);  // [16][64]
            float s = 0.0f;
            #pragma unroll
            for (int w = 0; w < NW; w++) s += sp[w * OUT + tid];
            float o = s * (1.0f / 16384.0f)
                    + row_mn * g_u[tid] + width * g_v[tid] + bias[tid];
            out[(size_t)r * OUT + tid] = o;
        }
        __syncthreads();                // spart/s_cnt reads done

        // re-zero aux for the next row (ordered before next binning by the
        // syncthreads in the next iteration's min/max reduce)
        #pragma unroll
        for (int k = 0; k < 4; k++) hist[tid + k * HB] = 0u;
    }
}

// ---------------------------------------------------------------------------
extern "C" void kernel_launch(void* const* d_in, const int* in_sizes, int n_in,
                              void* d_out, int out_size) {
    const float* x    = (const float*)d_in[0];   // [4096, 16384]
    const float* W    = (const float*)d_in[1];   // [64, 257]
    const float* bias = (const float*)d_in[2];   // [64]
    float* out = (float*)d_out;                  // [4096, 64]

    const int dyn_smem = (2 * HALF + 2048) * 4;  // 64 KB ring + 8 KB aux = 72 KB
    cudaFuncSetAttribute(fused_kernel, cudaFuncAttributeMaxDynamicSharedMemorySize, dyn_smem);

    fused_kernel<<<GRID, HB, dyn_smem>>>(x, W, bias, out);
}